// round 1
// baseline (speedup 1.0000x reference)
#include <cuda_runtime.h>
#include <math.h>

#define N     8192
#define D     128
#define TWON  16384

// exp(2.0) to float precision — the diagonal term exp(<h_i,h_i>/t) with t=0.5
// and ||h_i||=1 (post-normalize, error ~1e-7 -> 1e-10 relative vs denom ~16600).
#define DIAG_EXP2 7.38905609893065f

// -------- persistent device scratch (no allocations allowed) --------
__device__ float g_H[TWON * D];     // normalized rows: h1n (0..N-1), h2n (N..2N-1)
__device__ float g_pos[N];          // <h1n_i, h2n_i>
__device__ float g_rowsum[TWON];    // sum_j exp(2 * <H_i, H_j>)   (incl. diagonal)

// ============================================================
// Kernel A: normalize rows + positive-pair dot. One warp per pair.
// ============================================================
__global__ void nt_norm_kernel(const float* __restrict__ h1,
                               const float* __restrict__ h2) {
    int warp = (blockIdx.x * blockDim.x + threadIdx.x) >> 5;
    int lane = threadIdx.x & 31;
    if (warp >= N) return;

    float4 a = ((const float4*)(h1 + (size_t)warp * D))[lane];
    float4 b = ((const float4*)(h2 + (size_t)warp * D))[lane];

    float sa = a.x*a.x + a.y*a.y + a.z*a.z + a.w*a.w;
    float sb = b.x*b.x + b.y*b.y + b.z*b.z + b.w*b.w;
    float sd = a.x*b.x + a.y*b.y + a.z*b.z + a.w*b.w;

    #pragma unroll
    for (int o = 16; o; o >>= 1) {
        sa += __shfl_xor_sync(0xffffffffu, sa, o);
        sb += __shfl_xor_sync(0xffffffffu, sb, o);
        sd += __shfl_xor_sync(0xffffffffu, sd, o);
    }

    float ra = 1.0f / fmaxf(sqrtf(sa), 1e-12f);
    float rb = 1.0f / fmaxf(sqrtf(sb), 1e-12f);

    float4 an = make_float4(a.x*ra, a.y*ra, a.z*ra, a.w*ra);
    float4 bn = make_float4(b.x*rb, b.y*rb, b.z*rb, b.w*rb);

    ((float4*)(g_H + (size_t)warp * D))[lane]       = an;
    ((float4*)(g_H + (size_t)(warp + N) * D))[lane] = bn;

    if (lane == 0) g_pos[warp] = sd * ra * rb;
}

// ============================================================
// Kernel B: fused GEMM + exp + row-sum.
// Each CTA owns 128 i-rows, loops over all 128 j-tiles.
// smem layout is k-major (As[k][i], Bs[k][j]) -> float4 frag loads
// with the split-tile pattern (i = ty*4..+3 and 64+ty*4..+3) are
// contiguous-16B-per-lane => conflict-free.
// ============================================================
__global__ void __launch_bounds__(256, 1)
nt_gemm_kernel() {
    extern __shared__ float smem[];
    float* As = smem;            // [128 k][128 i]
    float* Bs = smem + D * 128;  // [128 k][128 j]

    const int tid = threadIdx.x;
    const int tx  = tid & 15;    // j group
    const int ty  = tid >> 4;    // i group
    const int i0  = blockIdx.x * 128;

    // ---- load I-tile once, transposed into k-major ----
    // lanes vary i (contiguous) => smem stores are conflict-free;
    // gmem side is L2-resident so the 50% sector efficiency is cheap.
    #pragma unroll
    for (int l = tid; l < 128 * 32; l += 256) {
        int i  = l & 127;
        int kq = l >> 7;
        float4 v = *(const float4*)(g_H + (size_t)(i0 + i) * D + kq * 4);
        As[(kq*4 + 0) * 128 + i] = v.x;
        As[(kq*4 + 1) * 128 + i] = v.y;
        As[(kq*4 + 2) * 128 + i] = v.z;
        As[(kq*4 + 3) * 128 + i] = v.w;
    }

    float rs[8];
    #pragma unroll
    for (int m = 0; m < 8; ++m) rs[m] = 0.0f;

    for (int jt = 0; jt < TWON / 128; ++jt) {
        __syncthreads();  // previous compute done before overwriting Bs
        #pragma unroll
        for (int l = tid; l < 128 * 32; l += 256) {
            int j  = l & 127;
            int kq = l >> 7;
            float4 v = *(const float4*)(g_H + (size_t)(jt * 128 + j) * D + kq * 4);
            Bs[(kq*4 + 0) * 128 + j] = v.x;
            Bs[(kq*4 + 1) * 128 + j] = v.y;
            Bs[(kq*4 + 2) * 128 + j] = v.z;
            Bs[(kq*4 + 3) * 128 + j] = v.w;
        }
        __syncthreads();

        float acc[8][8];
        #pragma unroll
        for (int m = 0; m < 8; ++m)
            #pragma unroll
            for (int n = 0; n < 8; ++n) acc[m][n] = 0.0f;

        #pragma unroll 4
        for (int k = 0; k < D; ++k) {
            float4 a0 = *(const float4*)(As + k*128 + ty*4);
            float4 a1 = *(const float4*)(As + k*128 + 64 + ty*4);
            float4 b0 = *(const float4*)(Bs + k*128 + tx*4);
            float4 b1 = *(const float4*)(Bs + k*128 + 64 + tx*4);
            float av[8] = {a0.x, a0.y, a0.z, a0.w, a1.x, a1.y, a1.z, a1.w};
            float bv[8] = {b0.x, b0.y, b0.z, b0.w, b1.x, b1.y, b1.z, b1.w};
            #pragma unroll
            for (int m = 0; m < 8; ++m)
                #pragma unroll
                for (int n = 0; n < 8; ++n)
                    acc[m][n] = fmaf(av[m], bv[n], acc[m][n]);
        }

        // epilogue: exp(sim / t), t = 0.5 -> exp(2*acc); fold into row sums
        #pragma unroll
        for (int m = 0; m < 8; ++m) {
            float s = 0.0f;
            #pragma unroll
            for (int n = 0; n < 8; ++n)
                s += __expf(2.0f * acc[m][n]);
            rs[m] += s;
        }
    }

    // ---- reduce rs across the 16 tx-threads sharing each i ----
    __syncthreads();
    float* red = smem;  // reuse As region: 128 floats
    if (tid < 128) red[tid] = 0.0f;
    __syncthreads();
    #pragma unroll
    for (int m = 0; m < 8; ++m) {
        int i = (m < 4) ? (ty*4 + m) : (64 + ty*4 + (m - 4));
        atomicAdd(&red[i], rs[m]);
    }
    __syncthreads();
    if (tid < 128) g_rowsum[i0 + tid] = red[tid];
}

// ============================================================
// Kernel C: final loss = mean( log(rowsum - exp(2)) - 2*pos )
// ============================================================
__global__ void nt_loss_kernel(float* __restrict__ out) {
    __shared__ double sred[16];
    const int tid  = threadIdx.x;   // 512 threads
    const int lane = tid & 31;
    const int wid  = tid >> 5;

    double s = 0.0;
    for (int i = tid; i < TWON; i += 512) {
        float denom = g_rowsum[i] - DIAG_EXP2;
        float term  = logf(denom) - 2.0f * g_pos[i & (N - 1)];
        s += (double)term;
    }
    #pragma unroll
    for (int o = 16; o; o >>= 1)
        s += __shfl_xor_sync(0xffffffffu, s, o);
    if (lane == 0) sred[wid] = s;
    __syncthreads();
    if (wid == 0) {
        double t = (lane < 16) ? sred[lane] : 0.0;
        #pragma unroll
        for (int o = 8; o; o >>= 1)
            t += __shfl_xor_sync(0xffffffffu, t, o);
        if (lane == 0) out[0] = (float)(t / (double)TWON);
    }
}

// ============================================================
extern "C" void kernel_launch(void* const* d_in, const int* in_sizes, int n_in,
                              void* d_out, int out_size) {
    const float* h1 = (const float*)d_in[0];
    const float* h2 = (const float*)d_in[1];
    float* out = (float*)d_out;

    nt_norm_kernel<<<N / 8, 256>>>(h1, h2);

    const int smem_bytes = 2 * D * 128 * (int)sizeof(float);  // 128 KB
    cudaFuncSetAttribute(nt_gemm_kernel,
                         cudaFuncAttributeMaxDynamicSharedMemorySize, smem_bytes);
    nt_gemm_kernel<<<TWON / 128, 256, smem_bytes>>>();

    nt_loss_kernel<<<1, 512>>>(out);
}

// round 3
// speedup vs baseline: 6.9577x; 6.9577x over previous
#include <cuda_runtime.h>
#include <cuda_bf16.h>
#include <math.h>
#include <stdint.h>

#define N     8192
#define D     128
#define TWON  16384

#define DIAG_EXP2  7.38905609893065f   // exp(2): diagonal of sim matrix
#define SQRT_SCALE 1.6986436f          // sqrt(2/ln2): acc = log2(exp arg)

// -------- persistent device scratch --------
__device__ __nv_bfloat16 g_Hb[TWON * D];   // normalized rows, pre-scaled by SQRT_SCALE
__device__ float g_pos[N];
__device__ float g_rowsum[TWON];

// ============================================================
// helpers (baseline PTX only: sm_75/sm_80 class instructions)
// ============================================================
__device__ __forceinline__ uint32_t smem_u32(const void* p) {
    uint32_t a;
    asm("{ .reg .u64 t; cvta.to.shared.u64 t, %1; cvt.u32.u64 %0, t; }" : "=r"(a) : "l"(p));
    return a;
}
__device__ __forceinline__ void cp_async16(uint32_t saddr, const void* gaddr) {
    asm volatile("cp.async.cg.shared.global [%0], [%1], 16;" :: "r"(saddr), "l"(gaddr) : "memory");
}
#define CP_COMMIT() asm volatile("cp.async.commit_group;" ::: "memory")
#define CP_WAIT0()  asm volatile("cp.async.wait_group 0;" ::: "memory")

__device__ __forceinline__ void ldmatrix_x4(uint32_t& r0, uint32_t& r1, uint32_t& r2,
                                            uint32_t& r3, uint32_t addr) {
    asm volatile("ldmatrix.sync.aligned.m8n8.x4.shared.b16 {%0,%1,%2,%3}, [%4];"
                 : "=r"(r0), "=r"(r1), "=r"(r2), "=r"(r3) : "r"(addr));
}
__device__ __forceinline__ void mma_bf16(float* c, const uint32_t* a, const uint32_t* b) {
    asm volatile("mma.sync.aligned.m16n8k16.row.col.f32.bf16.bf16.f32 "
                 "{%0,%1,%2,%3}, {%4,%5,%6,%7}, {%8,%9}, {%0,%1,%2,%3};"
                 : "+f"(c[0]), "+f"(c[1]), "+f"(c[2]), "+f"(c[3])
                 : "r"(a[0]), "r"(a[1]), "r"(a[2]), "r"(a[3]), "r"(b[0]), "r"(b[1]));
}
__device__ __forceinline__ float ex2f(float x) {
    float y;
    asm("ex2.approx.ftz.f32 %0, %1;" : "=f"(y) : "f"(x));
    return y;
}

// ============================================================
// Kernel A: normalize + pre-scale to bf16, positive-pair dot
// ============================================================
__global__ void nt_norm_kernel(const float* __restrict__ h1,
                               const float* __restrict__ h2) {
    int warp = (blockIdx.x * blockDim.x + threadIdx.x) >> 5;
    int lane = threadIdx.x & 31;
    if (warp >= N) return;

    float4 a = ((const float4*)(h1 + (size_t)warp * D))[lane];
    float4 b = ((const float4*)(h2 + (size_t)warp * D))[lane];

    float sa = a.x*a.x + a.y*a.y + a.z*a.z + a.w*a.w;
    float sb = b.x*b.x + b.y*b.y + b.z*b.z + b.w*b.w;
    float sd = a.x*b.x + a.y*b.y + a.z*b.z + a.w*b.w;
    #pragma unroll
    for (int o = 16; o; o >>= 1) {
        sa += __shfl_xor_sync(0xffffffffu, sa, o);
        sb += __shfl_xor_sync(0xffffffffu, sb, o);
        sd += __shfl_xor_sync(0xffffffffu, sd, o);
    }
    float ra = 1.0f / fmaxf(sqrtf(sa), 1e-12f);
    float rb = 1.0f / fmaxf(sqrtf(sb), 1e-12f);
    if (lane == 0) g_pos[warp] = sd * ra * rb;

    float fa = ra * SQRT_SCALE, fb = rb * SQRT_SCALE;
    union { __nv_bfloat162 b2[2]; uint2 u; } pa, pb;
    pa.b2[0] = __floats2bfloat162_rn(a.x*fa, a.y*fa);
    pa.b2[1] = __floats2bfloat162_rn(a.z*fa, a.w*fa);
    pb.b2[0] = __floats2bfloat162_rn(b.x*fb, b.y*fb);
    pb.b2[1] = __floats2bfloat162_rn(b.z*fb, b.w*fb);
    ((uint2*)(g_Hb + (size_t)warp * D))[lane]       = pa.u;
    ((uint2*)(g_Hb + (size_t)(warp + N) * D))[lane] = pb.u;
}

// ============================================================
// Kernel B: mma.sync bf16 GEMM + exp2 + row-sum (register accum)
//   CTA: 128 i-rows x 128 j-cols per tile, 128 tiles.
//   Warps: 4 m-groups (32 rows) x 2 n-groups (64 cols).
//   A fragments persistent in registers (loaded once).
//   B smem double-buffered via cp.async; rows padded to 136 bf16
//   (272B -> ldmatrix conflict-free).
// ============================================================
#define PADROW   136                    // bf16 elems per smem row
#define ROWB     (PADROW * 2)           // 272 bytes
#define A_OFF    0
#define A_BYTES  (128 * ROWB)           // 34816
#define B_OFF    A_BYTES
#define B_BYTES  (128 * ROWB)
#define RED_OFF  (B_OFF + 2 * B_BYTES)  // reuse after loop? placed after buffers
#define SMEM_SZ  (RED_OFF + 2 * 128 * 4)

__device__ __forceinline__ void cp_tile(uint32_t sbase, const __nv_bfloat16* src, int tid) {
    // 128 rows x 16 chunks of 16B
    #pragma unroll
    for (int c = tid; c < 2048; c += 256) {
        int r  = c >> 4;
        int kc = c & 15;
        cp_async16(sbase + r * ROWB + kc * 16, src + (size_t)r * D + kc * 8);
    }
}

__global__ void __launch_bounds__(256, 1) nt_gemm_mma() {
    extern __shared__ char smem[];
    uint32_t sb = smem_u32(smem);
    const int tid    = threadIdx.x;
    const int lane   = tid & 31;
    const int wid    = tid >> 5;
    const int warp_m = wid & 3;      // 0..3 -> rows warp_m*32
    const int warp_n = wid >> 2;     // 0..1 -> cols warp_n*64
    const int i0     = blockIdx.x * 128;

    // ---- prologue: load A tile + first B tile ----
    cp_tile(sb + A_OFF, g_Hb + (size_t)i0 * D, tid);
    cp_tile(sb + B_OFF, g_Hb, tid);
    CP_COMMIT();
    CP_WAIT0();
    __syncthreads();

    // ---- load all A fragments into registers (2 m-atoms x 8 k-steps) ----
    // ldmatrix x4 address: row = base_m + lane%16, col byte = (lane>>4)*16 + kst*32
    uint32_t afrag[8][2][4];
    {
        uint32_t abase = sb + A_OFF + (warp_m * 32 + (lane & 15)) * ROWB + (lane >> 4) * 16;
        #pragma unroll
        for (int kst = 0; kst < 8; ++kst)
            #pragma unroll
            for (int ma = 0; ma < 2; ++ma)
                ldmatrix_x4(afrag[kst][ma][0], afrag[kst][ma][1],
                            afrag[kst][ma][2], afrag[kst][ma][3],
                            abase + ma * 16 * ROWB + kst * 32);
    }

    float rs[4] = {0.f, 0.f, 0.f, 0.f};
    // B ldmatrix base: row j = warp_n*64 + pair*16 + lane%16, col = kst*16 + (lane>>4)*8
    uint32_t bbase0 = sb + B_OFF + (warp_n * 64 + (lane & 15)) * ROWB + (lane >> 4) * 16;

    for (int t = 0; t < 128; ++t) {
        if (t + 1 < 128) {
            cp_tile(sb + B_OFF + ((t + 1) & 1) * B_BYTES,
                    g_Hb + (size_t)(t + 1) * 128 * D, tid);
            CP_COMMIT();
        }

        uint32_t bbase = bbase0 + (t & 1) * B_BYTES;
        float acc[2][8][4];
        #pragma unroll
        for (int ma = 0; ma < 2; ++ma)
            #pragma unroll
            for (int na = 0; na < 8; ++na)
                #pragma unroll
                for (int q = 0; q < 4; ++q) acc[ma][na][q] = 0.f;

        #pragma unroll
        for (int kst = 0; kst < 8; ++kst) {
            uint32_t b[8][2];
            #pragma unroll
            for (int pr = 0; pr < 4; ++pr) {
                uint32_t r0, r1, r2, r3;
                ldmatrix_x4(r0, r1, r2, r3, bbase + pr * 16 * ROWB + kst * 32);
                b[pr*2    ][0] = r0; b[pr*2    ][1] = r2;
                b[pr*2 + 1][0] = r1; b[pr*2 + 1][1] = r3;
            }
            #pragma unroll
            for (int ma = 0; ma < 2; ++ma)
                #pragma unroll
                for (int na = 0; na < 8; ++na)
                    mma_bf16(acc[ma][na], afrag[kst][ma], b[na]);
        }

        // epilogue: exp2 of accumulators, fold into per-lane row sums.
        // acc[ma][na] lane layout: c0,c1 -> row (lane>>2)+ma*16, c2,c3 -> +8
        #pragma unroll
        for (int ma = 0; ma < 2; ++ma) {
            float s0 = 0.f, s1 = 0.f;
            #pragma unroll
            for (int na = 0; na < 8; ++na) {
                s0 += ex2f(acc[ma][na][0]) + ex2f(acc[ma][na][1]);
                s1 += ex2f(acc[ma][na][2]) + ex2f(acc[ma][na][3]);
            }
            rs[ma*2]     += s0;
            rs[ma*2 + 1] += s1;
        }

        CP_WAIT0();
        __syncthreads();
    }

    // ---- reduce rs across the 4 lanes of each quad (same rows, diff cols) ----
    #pragma unroll
    for (int i = 0; i < 4; ++i) {
        rs[i] += __shfl_xor_sync(0xffffffffu, rs[i], 1);
        rs[i] += __shfl_xor_sync(0xffffffffu, rs[i], 2);
    }
    float* red = (float*)(smem + RED_OFF);
    if ((lane & 3) == 0) {
        int r8 = lane >> 2;
        #pragma unroll
        for (int ma = 0; ma < 2; ++ma)
            #pragma unroll
            for (int p = 0; p < 2; ++p)
                red[warp_n * 128 + warp_m * 32 + ma * 16 + p * 8 + r8] = rs[ma*2 + p];
    }
    __syncthreads();
    if (tid < 128) g_rowsum[i0 + tid] = red[tid] + red[128 + tid];
}

// ============================================================
// Kernel C: loss = mean( log(rowsum - exp(2)) - 2*pos )
// ============================================================
__global__ void nt_loss_kernel(float* __restrict__ out) {
    __shared__ double sred[16];
    const int tid  = threadIdx.x;
    const int lane = tid & 31;
    const int wid  = tid >> 5;

    double s = 0.0;
    for (int i = tid; i < TWON; i += 512) {
        float denom = g_rowsum[i] - DIAG_EXP2;
        float term  = logf(denom) - 2.0f * g_pos[i & (N - 1)];
        s += (double)term;
    }
    #pragma unroll
    for (int o = 16; o; o >>= 1) s += __shfl_xor_sync(0xffffffffu, s, o);
    if (lane == 0) sred[wid] = s;
    __syncthreads();
    if (wid == 0) {
        double t = (lane < 16) ? sred[lane] : 0.0;
        #pragma unroll
        for (int o = 8; o; o >>= 1) t += __shfl_xor_sync(0xffffffffu, t, o);
        if (lane == 0) out[0] = (float)(t / (double)TWON);
    }
}

// ============================================================
extern "C" void kernel_launch(void* const* d_in, const int* in_sizes, int n_in,
                              void* d_out, int out_size) {
    const float* h1 = (const float*)d_in[0];
    const float* h2 = (const float*)d_in[1];
    float* out = (float*)d_out;

    nt_norm_kernel<<<N / 8, 256>>>(h1, h2);

    cudaFuncSetAttribute(nt_gemm_mma,
                         cudaFuncAttributeMaxDynamicSharedMemorySize, SMEM_SZ);
    nt_gemm_mma<<<TWON / 128, 256, SMEM_SZ>>>();

    nt_loss_kernel<<<1, 512>>>(out);
}